// round 5
// baseline (speedup 1.0000x reference)
#include <cuda_runtime.h>
#include <cuda_fp16.h>
#include <cstdint>

#define Ss 2048
#define Dd 64
constexpr int BH  = 32;
constexpr int QT  = 32;            // q rows per CTA
constexpr int KT  = 128;           // k cols per tile
constexpr int NTH = 256;           // 8 warps: 2 row-groups x 4 col-quarters
constexpr long long OUT_ELEMS = (long long)BH * Ss * Dd;
constexpr long long ATT_ELEMS = (long long)BH * Ss * (long long)Ss;

// fp16 / uint8 scratch (static device memory — allowed)
__device__ __half g_qh[(size_t)BH * Ss * Dd];    // pre-scaled by 1/8
__device__ __half g_kh[(size_t)BH * Ss * Dd];
__device__ __half g_vh[(size_t)BH * Ss * Dd];
__device__ unsigned char g_m8[(size_t)2 * Ss * Ss];

// smem layout (bytes)
constexpr int OFF_RED = 0;                        // srows[128] floats, srinv[32] at +512
constexpr int OFF_Q   = 1024;                     // 32 x 144
constexpr int KSTG    = 128 * 144;                // 18432
constexpr int OFF_K   = OFF_Q + 32 * 144;         // 5632 ; 2 stages
constexpr int OFF_V   = OFF_K + 2 * KSTG;         // 42496 ; 2 stages
constexpr int MSTG    = 32 * 144;                 // 4608
constexpr int OFF_M   = OFF_V + 2 * KSTG;         // 79360 ; 2 stages
constexpr int USTR    = 4144;                     // U row stride bytes (1036 words: conflict-free)
constexpr int OFF_U   = OFF_M + 2 * MSTG;         // 88576
constexpr int SMEM_BYTES = OFF_U + QT * USTR;     // 221184

__device__ __forceinline__ uint32_t smem_u32(const void* p) {
    uint32_t a;
    asm("{ .reg .u64 t; cvta.to.shared.u64 t, %1; cvt.u32.u64 %0, t; }" : "=r"(a) : "l"(p));
    return a;
}
__device__ __forceinline__ void ldsm4(uint32_t r[4], uint32_t a) {
    asm volatile("ldmatrix.sync.aligned.m8n8.x4.shared.b16 {%0,%1,%2,%3}, [%4];"
                 : "=r"(r[0]), "=r"(r[1]), "=r"(r[2]), "=r"(r[3]) : "r"(a) : "memory");
}
__device__ __forceinline__ void ldsm4t(uint32_t r[4], uint32_t a) {
    asm volatile("ldmatrix.sync.aligned.m8n8.x4.trans.shared.b16 {%0,%1,%2,%3}, [%4];"
                 : "=r"(r[0]), "=r"(r[1]), "=r"(r[2]), "=r"(r[3]) : "r"(a) : "memory");
}
__device__ __forceinline__ void mma16816(float c[4], const uint32_t a[4], uint32_t b0, uint32_t b1) {
    asm volatile(
        "mma.sync.aligned.m16n8k16.row.col.f32.f16.f16.f32 "
        "{%0,%1,%2,%3}, {%4,%5,%6,%7}, {%8,%9}, {%0,%1,%2,%3};"
        : "+f"(c[0]), "+f"(c[1]), "+f"(c[2]), "+f"(c[3])
        : "r"(a[0]), "r"(a[1]), "r"(a[2]), "r"(a[3]), "r"(b0), "r"(b1));
}
__device__ __forceinline__ uint32_t packh2(float x, float y) {
    __half2 h = __floats2half2_rn(x, y);
    return *(uint32_t*)&h;
}
#define CPA16(dst, src) asm volatile("cp.async.cg.shared.global [%0], [%1], 16;" :: "r"(dst), "l"(src))
#define CP_COMMIT()     asm volatile("cp.async.commit_group;" ::: "memory")
#define CP_WAIT0()      asm volatile("cp.async.wait_group 0;" ::: "memory")

// ---------------- merged pre-convert kernel ----------------
constexpr int QKV_BLOCKS  = 3 * (BH * Ss * Dd / 4) / 256;       // 12288
constexpr int MASK_BLOCKS = (2 * Ss * Ss / 4) / 256;            // 8192

__global__ void __launch_bounds__(256) cvt_all(const float* __restrict__ Q,
                                               const float* __restrict__ K,
                                               const float* __restrict__ V,
                                               const int* __restrict__ M)
{
    if (blockIdx.x < QKV_BLOCKS) {
        const int n4 = BH * Ss * Dd / 4;
        int id = blockIdx.x * 256 + threadIdx.x;
        const float* src; __half* dst; float s;
        int i = id;
        if (id < n4)          { src = Q; dst = g_qh; s = 0.125f; }
        else if (id < 2 * n4) { src = K; dst = g_kh; s = 1.f; i -= n4; }
        else                  { src = V; dst = g_vh; s = 1.f; i -= 2 * n4; }
        float4 v = ((const float4*)src)[i];
        uint2 u; u.x = packh2(v.x * s, v.y * s); u.y = packh2(v.z * s, v.w * s);
        ((uint2*)dst)[i] = u;
    } else {
        int i = (blockIdx.x - QKV_BLOCKS) * 256 + threadIdx.x;
        int4 m = ((const int4*)M)[i];
        uchar4 o; o.x = (unsigned char)m.x; o.y = (unsigned char)m.y;
        o.z = (unsigned char)m.z; o.w = (unsigned char)m.w;
        ((uchar4*)g_m8)[i] = o;
    }
}

extern __shared__ __align__(16) char sm[];

__global__ void __launch_bounds__(NTH, 1)
attn_kernel(float* __restrict__ out, float* __restrict__ att)
{
    const int tid  = threadIdx.x;
    const int lane = tid & 31;
    const int warp = tid >> 5;
    const int g    = lane >> 2;
    const int tg   = lane & 3;
    const int lm   = lane >> 3;
    const int ll   = lane & 7;
    const int rgrp = warp & 1;         // q-row group (16 rows)
    const int h    = warp >> 1;        // k-col quarter (32 cols)

    const int q0 = blockIdx.x * QT;
    const int bh = blockIdx.y;
    const int b  = bh >> 4;

    const uint32_t smb = smem_u32(sm);
    float* srows = (float*)(sm + OFF_RED);          // [4][32]
    float* srinv = (float*)(sm + OFF_RED + 512);    // [32]

    const __half* qsrc = g_qh + ((size_t)bh * Ss + q0) * Dd;
    const __half* ksrc = g_kh + (size_t)bh * Ss * Dd;
    const __half* vsrc = g_vh + (size_t)bh * Ss * Dd;
    const unsigned char* msrc = g_m8 + (size_t)b * Ss * Ss + (size_t)q0 * Ss;
    float* attg = att ? (att + (size_t)bh * Ss * (size_t)Ss) : nullptr;

    // fragment address bases
    const uint32_t qfr = smb + OFF_Q + (uint32_t)((rgrp * 16 + (lm & 1) * 8 + ll) * 144 + (lm >> 1) * 16);
    const uint32_t kfr = smb + OFF_K + (uint32_t)((h * 32 + (lm >> 1) * 8 + ll) * 144 + (lm & 1) * 16);
    const uint32_t vfr = smb + OFF_V + (uint32_t)((h * 32 + (lm & 1) * 8 + ll) * 144 + (lm >> 1) * 16);

    const int r0 = rgrp * 16 + g;      // thread's two q rows: r0, r0+8
    const int r1 = r0 + 8;

    // ---- prologue: Q + K0 + V0 + M0 via cp.async ----
    {
        int r = tid >> 3, c = tid & 7;
        CPA16(smb + OFF_Q + r * 144 + c * 16, qsrc + r * 64 + c * 8);           // 32 rows
        CPA16(smb + OFF_M + r * 144 + c * 16, msrc + (size_t)r * Ss + c * 16);  // 32 rows mask
    }
    #pragma unroll
    for (int i = 0; i < 4; i++) {
        int idx = tid + i * NTH; int r = idx >> 3, c = idx & 7;
        CPA16(smb + OFF_K + r * 144 + c * 16, ksrc + (size_t)r * 64 + c * 8);
        CPA16(smb + OFF_V + r * 144 + c * 16, vsrc + (size_t)r * 64 + c * 8);
    }
    CP_COMMIT();
    CP_WAIT0();
    __syncthreads();

    uint32_t aQ[4][4];
    #pragma unroll
    for (int kc = 0; kc < 4; kc++) ldsm4(aQ[kc], qfr + kc * 32);

    float o[8][4];
    #pragma unroll
    for (int j = 0; j < 8; j++)
        #pragma unroll
        for (int q = 0; q < 4; q++) o[j][q] = 0.f;
    float rs0 = 0.f, rs1 = 0.f;

    // ================= single mainloop =================
    for (int t = 0; t < Ss / KT; t++) {
        const int stg = t & 1;
        if (t + 1 < Ss / KT) {
            const int ns = (t + 1) & 1;
            #pragma unroll
            for (int i = 0; i < 4; i++) {
                int idx = tid + i * NTH; int r = idx >> 3, cc = idx & 7;
                CPA16(smb + OFF_K + ns * KSTG + r * 144 + cc * 16,
                      ksrc + ((size_t)(t + 1) * KT + r) * 64 + cc * 8);
                CPA16(smb + OFF_V + ns * KSTG + r * 144 + cc * 16,
                      vsrc + ((size_t)(t + 1) * KT + r) * 64 + cc * 8);
            }
            {
                int r = tid >> 3, cc = tid & 7;
                CPA16(smb + OFF_M + ns * MSTG + r * 144 + cc * 16,
                      msrc + (size_t)r * Ss + (t + 1) * KT + cc * 16);
            }
            CP_COMMIT();
        }

        // QK: warp tile 16(q) x 32(k)
        float c4[4][4];
        #pragma unroll
        for (int j = 0; j < 4; j++)
            #pragma unroll
            for (int q = 0; q < 4; q++) c4[j][q] = 0.f;

        #pragma unroll
        for (int kc = 0; kc < 4; kc++)
            #pragma unroll
            for (int np = 0; np < 2; np++) {
                uint32_t bf[4];
                ldsm4(bf, kfr + stg * KSTG + np * 2304 + kc * 32);
                mma16816(c4[2 * np],     aQ[kc], bf[0], bf[1]);
                mma16816(c4[2 * np + 1], aQ[kc], bf[2], bf[3]);
            }

        // epilogue: u = mask ? exp(e) : 0 (unnormalized); fp16 pack -> U smem + rowsums
        uint32_t ulo[4], uhi[4];
        #pragma unroll
        for (int nt = 0; nt < 4; nt++) {
            const int colb = 32 * h + 8 * nt + 2 * tg;
            uint16_t m0 = *(const uint16_t*)(sm + OFF_M + stg * MSTG + r0 * 144 + colb);
            uint16_t m1 = *(const uint16_t*)(sm + OFF_M + stg * MSTG + r1 * 144 + colb);
            float u0 = (m0 & 0xFF) ? __expf(c4[nt][0]) : 0.f;
            float u1 = (m0 >> 8)   ? __expf(c4[nt][1]) : 0.f;
            float u2 = (m1 & 0xFF) ? __expf(c4[nt][2]) : 0.f;
            float u3 = (m1 >> 8)   ? __expf(c4[nt][3]) : 0.f;
            rs0 += u0 + u1; rs1 += u2 + u3;
            ulo[nt] = packh2(u0, u1); uhi[nt] = packh2(u2, u3);
            *(uint32_t*)(sm + OFF_U + r0 * USTR + (t * KT + colb) * 2) = ulo[nt];
            *(uint32_t*)(sm + OFF_U + r1 * USTR + (t * KT + colb) * 2) = uhi[nt];
        }

        // PV: A = packed u, B = V^T (warp's 32 k-rows), accumulate over all 64 d
        #pragma unroll
        for (int kc = 0; kc < 2; kc++) {
            uint32_t a[4] = { ulo[2 * kc], uhi[2 * kc], ulo[2 * kc + 1], uhi[2 * kc + 1] };
            #pragma unroll
            for (int np = 0; np < 4; np++) {
                uint32_t bf[4];
                ldsm4t(bf, vfr + stg * KSTG + kc * 2304 + np * 32);
                mma16816(o[2 * np],     a, bf[0], bf[1]);
                mma16816(o[2 * np + 1], a, bf[2], bf[3]);
            }
        }

        if (t + 1 < Ss / KT) { CP_WAIT0(); __syncthreads(); }
    }

    // ---- row sums -> reciprocals ----
    rs0 += __shfl_xor_sync(0xffffffffu, rs0, 1); rs0 += __shfl_xor_sync(0xffffffffu, rs0, 2);
    rs1 += __shfl_xor_sync(0xffffffffu, rs1, 1); rs1 += __shfl_xor_sync(0xffffffffu, rs1, 2);
    __syncthreads();
    if (tg == 0) { srows[h * 32 + r0] = rs0; srows[h * 32 + r1] = rs1; }
    __syncthreads();
    if (tid < 32) {
        float s = srows[tid] + srows[32 + tid] + srows[64 + tid] + srows[96 + tid];
        srinv[tid] = (s > 0.f) ? (1.0f / s) : 0.f;
    }
    __syncthreads();

    // ---- O partials from h>0 into stage (reuse K area) ----
    float* ost = (float*)(sm + OFF_K);           // 3 x [32][66]
    if (h > 0) {
        float* sh = ost + (h - 1) * 32 * 66;
        #pragma unroll
        for (int j = 0; j < 8; j++) {
            *(float2*)&sh[r0 * 66 + 8 * j + 2 * tg] = make_float2(o[j][0], o[j][1]);
            *(float2*)&sh[r1 * 66 + 8 * j + 2 * tg] = make_float2(o[j][2], o[j][3]);
        }
    }
    __syncthreads();

    // ---- O finalize (h==0 warps) ----
    if (out && h == 0) {
        const float rv0 = srinv[r0], rv1 = srinv[r1];
        float* og0 = out + ((size_t)bh * Ss + q0 + r0) * Dd;
        float* og1 = out + ((size_t)bh * Ss + q0 + r1) * Dd;
        #pragma unroll
        for (int j = 0; j < 8; j++) {
            float a0 = o[j][0], a1 = o[j][1], a2 = o[j][2], a3 = o[j][3];
            #pragma unroll
            for (int p = 0; p < 3; p++) {
                float2 s0 = *(float2*)&ost[p * 32 * 66 + r0 * 66 + 8 * j + 2 * tg];
                float2 s1 = *(float2*)&ost[p * 32 * 66 + r1 * 66 + 8 * j + 2 * tg];
                a0 += s0.x; a1 += s0.y; a2 += s1.x; a3 += s1.y;
            }
            *(float2*)(og0 + 8 * j + 2 * tg) = make_float2(a0 * rv0, a1 * rv0);
            *(float2*)(og1 + 8 * j + 2 * tg) = make_float2(a2 * rv1, a3 * rv1);
        }
    }

    // ---- attention writeout: U smem * rinv -> gmem ----
    if (attg) {
        const int r  = tid >> 3;
        const int ch = tid & 7;
        const float rv = srinv[r];
        const char* ub = sm + OFF_U + r * USTR;
        float* ar = attg + (size_t)(q0 + r) * Ss;
        #pragma unroll 4
        for (int j = 0; j < 32; j++) {
            int cidx = j * 8 + ch;                     // 0..255 (x8 cols)
            uint4 u4 = *(const uint4*)(ub + cidx * 16);
            float2 f0 = __half22float2(*(__half2*)&u4.x);
            float2 f1 = __half22float2(*(__half2*)&u4.y);
            float2 f2 = __half22float2(*(__half2*)&u4.z);
            float2 f3 = __half22float2(*(__half2*)&u4.w);
            float* dst = ar + cidx * 8;
            *(float4*)dst       = make_float4(f0.x * rv, f0.y * rv, f1.x * rv, f1.y * rv);
            *(float4*)(dst + 4) = make_float4(f2.x * rv, f2.y * rv, f3.x * rv, f3.y * rv);
        }
    }
}

extern "C" void kernel_launch(void* const* d_in, const int* in_sizes, int n_in,
                              void* d_out, int out_size)
{
    (void)in_sizes; (void)n_in;
    const float* Q = (const float*)d_in[0];
    const float* K = (const float*)d_in[1];
    const float* V = (const float*)d_in[2];
    const int*   M = (const int*)d_in[3];

    float* outp = nullptr;
    float* attp = nullptr;
    long long os = (long long)out_size;
    if (os >= OUT_ELEMS + ATT_ELEMS) {
        outp = (float*)d_out;
        attp = (float*)d_out + OUT_ELEMS;
    } else if (os >= ATT_ELEMS) {
        attp = (float*)d_out;
    } else {
        outp = (float*)d_out;
    }

    cvt_all<<<QKV_BLOCKS + MASK_BLOCKS, 256>>>(Q, K, V, M);

    cudaFuncSetAttribute(attn_kernel, cudaFuncAttributeMaxDynamicSharedMemorySize, SMEM_BYTES);
    dim3 grid(Ss / QT, BH);
    attn_kernel<<<grid, NTH, SMEM_BYTES>>>(outp, attp);
}

// round 6
// speedup vs baseline: 1.1656x; 1.1656x over previous
#include <cuda_runtime.h>
#include <cuda_fp16.h>
#include <cstdint>

#define Ss 2048
#define Dd 64
constexpr int BH  = 32;
constexpr int QT  = 64;            // q rows per CTA
constexpr int KT  = 128;           // k cols per tile
constexpr int NTH = 512;           // 16 warps: 4 row-groups x 4 col-groups
constexpr int NT  = Ss / KT;       // 16 tiles
constexpr long long OUT_ELEMS = (long long)BH * Ss * Dd;
constexpr long long ATT_ELEMS = (long long)BH * Ss * (long long)Ss;

// fp16 / uint8 scratch (static device memory — allowed)
__device__ __half g_qh[(size_t)BH * Ss * Dd];    // pre-scaled by 1/8
__device__ __half g_kh[(size_t)BH * Ss * Dd];
__device__ __half g_vh[(size_t)BH * Ss * Dd];
__device__ unsigned char g_m8[(size_t)2 * Ss * Ss];

// smem layout (bytes); row stride 144 B -> conflict-free ldmatrix
constexpr int OFF_RED = 0;                        // srows[4][64] + srinv[64]
constexpr int OFF_Q   = 1536;                     // 64 x 144
constexpr int KSTG    = 128 * 144;                // 18432
constexpr int OFF_K   = OFF_Q + 64 * 144;         // 10752 ; 3 stages
constexpr int OFF_V   = OFF_K + 3 * KSTG;         // 66048 ; 3 stages
constexpr int MSTG    = 64 * 144;                 // 9216
constexpr int OFF_M   = OFF_V + 3 * KSTG;         // 121344 ; 3 stages
constexpr int SMEM_BYTES = OFF_M + 3 * MSTG;      // 148992

__device__ __forceinline__ uint32_t smem_u32(const void* p) {
    uint32_t a;
    asm("{ .reg .u64 t; cvta.to.shared.u64 t, %1; cvt.u32.u64 %0, t; }" : "=r"(a) : "l"(p));
    return a;
}
__device__ __forceinline__ void ldsm4(uint32_t r[4], uint32_t a) {
    asm volatile("ldmatrix.sync.aligned.m8n8.x4.shared.b16 {%0,%1,%2,%3}, [%4];"
                 : "=r"(r[0]), "=r"(r[1]), "=r"(r[2]), "=r"(r[3]) : "r"(a) : "memory");
}
__device__ __forceinline__ void ldsm4t(uint32_t r[4], uint32_t a) {
    asm volatile("ldmatrix.sync.aligned.m8n8.x4.trans.shared.b16 {%0,%1,%2,%3}, [%4];"
                 : "=r"(r[0]), "=r"(r[1]), "=r"(r[2]), "=r"(r[3]) : "r"(a) : "memory");
}
__device__ __forceinline__ void mma16816(float c[4], const uint32_t a[4], uint32_t b0, uint32_t b1) {
    asm volatile(
        "mma.sync.aligned.m16n8k16.row.col.f32.f16.f16.f32 "
        "{%0,%1,%2,%3}, {%4,%5,%6,%7}, {%8,%9}, {%0,%1,%2,%3};"
        : "+f"(c[0]), "+f"(c[1]), "+f"(c[2]), "+f"(c[3])
        : "r"(a[0]), "r"(a[1]), "r"(a[2]), "r"(a[3]), "r"(b0), "r"(b1));
}
__device__ __forceinline__ uint32_t packh2(float x, float y) {
    __half2 h = __floats2half2_rn(x, y);
    return *(uint32_t*)&h;
}
#define CPA16(dst, src) asm volatile("cp.async.cg.shared.global [%0], [%1], 16;" :: "r"(dst), "l"(src))
#define CP_COMMIT()     asm volatile("cp.async.commit_group;" ::: "memory")
#define CP_WAIT0()      asm volatile("cp.async.wait_group 0;" ::: "memory")
#define CP_WAIT1()      asm volatile("cp.async.wait_group 1;" ::: "memory")

// ---------------- merged pre-convert kernel ----------------
constexpr int QKV_BLOCKS  = 3 * (BH * Ss * Dd / 4) / 256;       // 12288
constexpr int MASK_BLOCKS = (2 * Ss * Ss / 4) / 256;            // 8192

__global__ void __launch_bounds__(256) cvt_all(const float* __restrict__ Q,
                                               const float* __restrict__ K,
                                               const float* __restrict__ V,
                                               const int* __restrict__ M)
{
    if (blockIdx.x < QKV_BLOCKS) {
        const int n4 = BH * Ss * Dd / 4;
        int id = blockIdx.x * 256 + threadIdx.x;
        const float* src; __half* dst; float s;
        int i = id;
        if (id < n4)          { src = Q; dst = g_qh; s = 0.125f; }
        else if (id < 2 * n4) { src = K; dst = g_kh; s = 1.f; i -= n4; }
        else                  { src = V; dst = g_vh; s = 1.f; i -= 2 * n4; }
        float4 v = ((const float4*)src)[i];
        uint2 u; u.x = packh2(v.x * s, v.y * s); u.y = packh2(v.z * s, v.w * s);
        ((uint2*)dst)[i] = u;
    } else {
        int i = (blockIdx.x - QKV_BLOCKS) * 256 + threadIdx.x;
        int4 m = ((const int4*)M)[i];
        uchar4 o; o.x = (unsigned char)m.x; o.y = (unsigned char)m.y;
        o.z = (unsigned char)m.z; o.w = (unsigned char)m.w;
        ((uchar4*)g_m8)[i] = o;
    }
}

extern __shared__ __align__(16) char sm[];

__global__ void __launch_bounds__(NTH, 1)
attn_kernel(float* __restrict__ out, float* __restrict__ att)
{
    const int tid  = threadIdx.x;
    const int lane = tid & 31;
    const int warp = tid >> 5;
    const int g    = lane >> 2;
    const int tg   = lane & 3;
    const int lm   = lane >> 3;
    const int ll   = lane & 7;
    const int rgrp = warp >> 2;        // q-row group (16 rows), 0..3
    const int h    = warp & 3;         // k-col group (32 cols), 0..3

    const int q0 = blockIdx.x * QT;
    const int bh = blockIdx.y;
    const int b  = bh >> 4;

    const uint32_t smb = smem_u32(sm);
    float* srows = (float*)(sm + OFF_RED);          // [4][64]
    float* srinv = (float*)(sm + OFF_RED + 1024);   // [64]

    const __half* qsrc = g_qh + ((size_t)bh * Ss + q0) * Dd;
    const __half* ksrc = g_kh + (size_t)bh * Ss * Dd;
    const __half* vsrc = g_vh + (size_t)bh * Ss * Dd;
    const unsigned char* msrc = g_m8 + (size_t)b * Ss * Ss + (size_t)q0 * Ss;
    float* attg = att ? (att + (size_t)bh * Ss * (size_t)Ss) : nullptr;

    // fragment address bases
    const uint32_t qfr = smb + OFF_Q + (uint32_t)((rgrp * 16 + (lm & 1) * 8 + ll) * 144 + (lm >> 1) * 16);
    const uint32_t kfr = smb + OFF_K + (uint32_t)((h * 32 + (lm >> 1) * 8 + ll) * 144 + (lm & 1) * 16);
    const uint32_t vfr = smb + OFF_V + (uint32_t)((h * 32 + (lm & 1) * 8 + ll) * 144 + (lm >> 1) * 16);

    const int r0 = rgrp * 16 + g;      // thread's two q rows: r0, r0+8
    const int r1 = r0 + 8;

    // ---- pass-1 prologue: G0 = Q + K0 + M0 ; G1 = K1 + M1 ----
    {
        int r = tid >> 3, c = tid & 7;
        CPA16(smb + OFF_Q + r * 144 + c * 16, qsrc + r * 64 + c * 8);
        CPA16(smb + OFF_M + r * 144 + c * 16, msrc + (size_t)r * Ss + c * 16);
    }
    #pragma unroll
    for (int i = 0; i < 2; i++) {
        int idx = tid + i * NTH; int r = idx >> 3, c = idx & 7;
        CPA16(smb + OFF_K + r * 144 + c * 16, ksrc + (size_t)r * 64 + c * 8);
    }
    CP_COMMIT();
    #pragma unroll
    for (int i = 0; i < 2; i++) {
        int idx = tid + i * NTH; int r = idx >> 3, c = idx & 7;
        CPA16(smb + OFF_K + KSTG + r * 144 + c * 16, ksrc + ((size_t)KT + r) * 64 + c * 8);
    }
    {
        int r = tid >> 3, c = tid & 7;
        CPA16(smb + OFF_M + MSTG + r * 144 + c * 16, msrc + (size_t)r * Ss + KT + c * 16);
    }
    CP_COMMIT();
    CP_WAIT1();
    __syncthreads();

    uint32_t aQ[4][4];
    #pragma unroll
    for (int kc = 0; kc < 4; kc++) ldsm4(aQ[kc], qfr + kc * 32);

    // ================= PASS 1: row sums =================
    float rs0 = 0.f, rs1 = 0.f;
    for (int t = 0; t < NT; t++) {
        const int stg = t % 3;
        if (t + 2 < NT) {
            const int ns = (t + 2) % 3;
            #pragma unroll
            for (int i = 0; i < 2; i++) {
                int idx = tid + i * NTH; int r = idx >> 3, cc = idx & 7;
                CPA16(smb + OFF_K + ns * KSTG + r * 144 + cc * 16,
                      ksrc + ((size_t)(t + 2) * KT + r) * 64 + cc * 8);
            }
            {
                int r = tid >> 3, cc = tid & 7;
                CPA16(smb + OFF_M + ns * MSTG + r * 144 + cc * 16,
                      msrc + (size_t)r * Ss + (t + 2) * KT + cc * 16);
            }
            CP_COMMIT();
        }

        float c4[4][4];
        #pragma unroll
        for (int j = 0; j < 4; j++)
            #pragma unroll
            for (int q = 0; q < 4; q++) c4[j][q] = 0.f;

        const uint32_t kb = kfr + stg * KSTG;
        #pragma unroll
        for (int kc = 0; kc < 4; kc++)
            #pragma unroll
            for (int np = 0; np < 2; np++) {
                uint32_t bf[4];
                ldsm4(bf, kb + np * 2304 + kc * 32);
                mma16816(c4[2 * np],     aQ[kc], bf[0], bf[1]);
                mma16816(c4[2 * np + 1], aQ[kc], bf[2], bf[3]);
            }

        const char* mb = sm + OFF_M + stg * MSTG;
        #pragma unroll
        for (int nt = 0; nt < 4; nt++) {
            const int colb = 32 * h + 8 * nt + 2 * tg;
            uint16_t m0 = *(const uint16_t*)(mb + r0 * 144 + colb);
            uint16_t m1 = *(const uint16_t*)(mb + r1 * 144 + colb);
            rs0 += ((m0 & 0xFF) ? __expf(c4[nt][0]) : 0.f) + ((m0 >> 8) ? __expf(c4[nt][1]) : 0.f);
            rs1 += ((m1 & 0xFF) ? __expf(c4[nt][2]) : 0.f) + ((m1 >> 8) ? __expf(c4[nt][3]) : 0.f);
        }

        if (t + 1 < NT) {
            if (t + 2 < NT) CP_WAIT1(); else CP_WAIT0();
            __syncthreads();
        }
    }

    // reduce quad, then 4 col-groups
    rs0 += __shfl_xor_sync(0xffffffffu, rs0, 1); rs0 += __shfl_xor_sync(0xffffffffu, rs0, 2);
    rs1 += __shfl_xor_sync(0xffffffffu, rs1, 1); rs1 += __shfl_xor_sync(0xffffffffu, rs1, 2);
    __syncthreads();
    if (tg == 0) { srows[h * 64 + r0] = rs0; srows[h * 64 + r1] = rs1; }
    __syncthreads();
    if (tid < 64) {
        float s = srows[tid] + srows[64 + tid] + srows[128 + tid] + srows[192 + tid];
        srinv[tid] = (s > 0.f) ? (1.0f / s) : 0.f;
    }
    __syncthreads();
    const float rinv0 = srinv[r0];
    const float rinv1 = srinv[r1];

    // ================= PASS 2: normalized att + O =================
    float o[8][4];
    #pragma unroll
    for (int j = 0; j < 8; j++)
        #pragma unroll
        for (int q = 0; q < 4; q++) o[j][q] = 0.f;

    // prologue: G0 = K0+V0+M0 ; G1 = K1+V1+M1
    #pragma unroll
    for (int s2 = 0; s2 < 2; s2++) {
        #pragma unroll
        for (int i = 0; i < 2; i++) {
            int idx = tid + i * NTH; int r = idx >> 3, cc = idx & 7;
            CPA16(smb + OFF_K + s2 * KSTG + r * 144 + cc * 16,
                  ksrc + ((size_t)s2 * KT + r) * 64 + cc * 8);
            CPA16(smb + OFF_V + s2 * KSTG + r * 144 + cc * 16,
                  vsrc + ((size_t)s2 * KT + r) * 64 + cc * 8);
        }
        {
            int r = tid >> 3, cc = tid & 7;
            CPA16(smb + OFF_M + s2 * MSTG + r * 144 + cc * 16,
                  msrc + (size_t)r * Ss + s2 * KT + cc * 16);
        }
        CP_COMMIT();
    }
    CP_WAIT1();
    __syncthreads();

    for (int t = 0; t < NT; t++) {
        const int stg = t % 3;
        if (t + 2 < NT) {
            const int ns = (t + 2) % 3;
            #pragma unroll
            for (int i = 0; i < 2; i++) {
                int idx = tid + i * NTH; int r = idx >> 3, cc = idx & 7;
                CPA16(smb + OFF_K + ns * KSTG + r * 144 + cc * 16,
                      ksrc + ((size_t)(t + 2) * KT + r) * 64 + cc * 8);
                CPA16(smb + OFF_V + ns * KSTG + r * 144 + cc * 16,
                      vsrc + ((size_t)(t + 2) * KT + r) * 64 + cc * 8);
            }
            {
                int r = tid >> 3, cc = tid & 7;
                CPA16(smb + OFF_M + ns * MSTG + r * 144 + cc * 16,
                      msrc + (size_t)r * Ss + (t + 2) * KT + cc * 16);
            }
            CP_COMMIT();
        }

        float c4[4][4];
        #pragma unroll
        for (int j = 0; j < 4; j++)
            #pragma unroll
            for (int q = 0; q < 4; q++) c4[j][q] = 0.f;

        const uint32_t kb = kfr + stg * KSTG;
        #pragma unroll
        for (int kc = 0; kc < 4; kc++)
            #pragma unroll
            for (int np = 0; np < 2; np++) {
                uint32_t bf[4];
                ldsm4(bf, kb + np * 2304 + kc * 32);
                mma16816(c4[2 * np],     aQ[kc], bf[0], bf[1]);
                mma16816(c4[2 * np + 1], aQ[kc], bf[2], bf[3]);
            }

        // epilogue: u = mask ? exp(e)*rinv : 0 ; write att ; pack for PV
        const char* mb = sm + OFF_M + stg * MSTG;
        float* ar0 = attg ? (attg + (size_t)(q0 + r0) * Ss + t * KT + 32 * h + 2 * tg) : nullptr;
        uint32_t ulo[4], uhi[4];
        #pragma unroll
        for (int nt = 0; nt < 4; nt++) {
            const int colb = 32 * h + 8 * nt + 2 * tg;
            uint16_t m0 = *(const uint16_t*)(mb + r0 * 144 + colb);
            uint16_t m1 = *(const uint16_t*)(mb + r1 * 144 + colb);
            float u0 = (m0 & 0xFF) ? __expf(c4[nt][0]) * rinv0 : 0.f;
            float u1 = (m0 >> 8)   ? __expf(c4[nt][1]) * rinv0 : 0.f;
            float u2 = (m1 & 0xFF) ? __expf(c4[nt][2]) * rinv1 : 0.f;
            float u3 = (m1 >> 8)   ? __expf(c4[nt][3]) * rinv1 : 0.f;
            if (ar0) {
                *(float2*)(ar0 + 8 * nt)          = make_float2(u0, u1);
                *(float2*)(ar0 + 8 * Ss + 8 * nt) = make_float2(u2, u3);
            }
            ulo[nt] = packh2(u0, u1); uhi[nt] = packh2(u2, u3);
        }

        // PV: A = packed normalized u, B = V^T (warp's 32 k-rows), full d=64
        const uint32_t vb = vfr + stg * KSTG;
        #pragma unroll
        for (int kc = 0; kc < 2; kc++) {
            uint32_t a[4] = { ulo[2 * kc], uhi[2 * kc], ulo[2 * kc + 1], uhi[2 * kc + 1] };
            #pragma unroll
            for (int np = 0; np < 4; np++) {
                uint32_t bf[4];
                ldsm4t(bf, vb + kc * 2304 + np * 32);
                mma16816(o[2 * np],     a, bf[0], bf[1]);
                mma16816(o[2 * np + 1], a, bf[2], bf[3]);
            }
        }

        if (t + 1 < NT) {
            if (t + 2 < NT) CP_WAIT1(); else CP_WAIT0();
            __syncthreads();
        }
    }

    // ---- combine 4 k-col groups of O via smem (reuse K area), write out ----
    __syncthreads();
    float* ost = (float*)(sm + OFF_K);            // 3 x [64][66]
    if (h > 0) {
        float* sh = ost + (h - 1) * 64 * 66;
        #pragma unroll
        for (int j = 0; j < 8; j++) {
            *(float2*)&sh[r0 * 66 + 8 * j + 2 * tg] = make_float2(o[j][0], o[j][1]);
            *(float2*)&sh[r1 * 66 + 8 * j + 2 * tg] = make_float2(o[j][2], o[j][3]);
        }
    }
    __syncthreads();
    if (out && h == 0) {
        float* og0 = out + ((size_t)bh * Ss + q0 + r0) * Dd;
        float* og1 = out + ((size_t)bh * Ss + q0 + r1) * Dd;
        #pragma unroll
        for (int j = 0; j < 8; j++) {
            float a0 = o[j][0], a1 = o[j][1], a2 = o[j][2], a3 = o[j][3];
            #pragma unroll
            for (int p = 0; p < 3; p++) {
                float2 s0 = *(float2*)&ost[p * 64 * 66 + r0 * 66 + 8 * j + 2 * tg];
                float2 s1 = *(float2*)&ost[p * 64 * 66 + r1 * 66 + 8 * j + 2 * tg];
                a0 += s0.x; a1 += s0.y; a2 += s1.x; a3 += s1.y;
            }
            *(float2*)(og0 + 8 * j + 2 * tg) = make_float2(a0, a1);
            *(float2*)(og1 + 8 * j + 2 * tg) = make_float2(a2, a3);
        }
    }
}

extern "C" void kernel_launch(void* const* d_in, const int* in_sizes, int n_in,
                              void* d_out, int out_size)
{
    (void)in_sizes; (void)n_in;
    const float* Q = (const float*)d_in[0];
    const float* K = (const float*)d_in[1];
    const float* V = (const float*)d_in[2];
    const int*   M = (const int*)d_in[3];

    float* outp = nullptr;
    float* attp = nullptr;
    long long os = (long long)out_size;
    if (os >= OUT_ELEMS + ATT_ELEMS) {
        outp = (float*)d_out;
        attp = (float*)d_out + OUT_ELEMS;
    } else if (os >= ATT_ELEMS) {
        attp = (float*)d_out;
    } else {
        outp = (float*)d_out;
    }

    cvt_all<<<QKV_BLOCKS + MASK_BLOCKS, 256>>>(Q, K, V, M);

    cudaFuncSetAttribute(attn_kernel, cudaFuncAttributeMaxDynamicSharedMemorySize, SMEM_BYTES);
    dim3 grid(Ss / QT, BH);
    attn_kernel<<<grid, NTH, SMEM_BYTES>>>(outp, attp);
}

// round 7
// speedup vs baseline: 1.3059x; 1.1204x over previous
#include <cuda_runtime.h>
#include <cuda_fp16.h>
#include <cstdint>

#define Ss 2048
#define Dd 64
constexpr int BH  = 32;
constexpr int QT  = 64;            // q rows per CTA
constexpr int KT  = 128;           // k cols per tile
constexpr int NTH = 256;           // 8 warps: 4 row-groups x 2 col-halves
constexpr int NT  = Ss / KT;       // 16
constexpr long long OUT_ELEMS = (long long)BH * Ss * Dd;
constexpr long long ATT_ELEMS = (long long)BH * Ss * (long long)Ss;

// fp16 / uint8 scratch (static device memory — allowed)
__device__ __align__(256) __half g_qh[(size_t)BH * Ss * Dd];   // pre-scaled by log2e/8
__device__ __align__(256) __half g_kh[(size_t)BH * Ss * Dd];
__device__ __align__(256) __half g_vh[(size_t)BH * Ss * Dd];
__device__ __align__(256) unsigned char g_m8[(size_t)2 * Ss * Ss];

// smem layout (bytes); row stride 144 B -> conflict-free ldmatrix
constexpr int OFF_RED = 0;                        // srows[2][64] + slog[64]
constexpr int OFF_Q   = 1024;                     // 64 x 144
constexpr int KSTG    = 128 * 144;                // 18432
constexpr int OFF_K   = OFF_Q + 64 * 144;         // 10240 ; 2 stages
constexpr int OFF_V   = OFF_K + 2 * KSTG;         // 47104 ; 2 stages
constexpr int MSTG    = 64 * 144;                 // 9216
constexpr int OFF_M   = OFF_V + 2 * KSTG;         // 83968 ; 2 stages
constexpr int SMEM_BYTES = OFF_M + 2 * MSTG;      // 102400 -> 2 CTAs/SM

__device__ __forceinline__ uint32_t smem_u32(const void* p) {
    uint32_t a;
    asm("{ .reg .u64 t; cvta.to.shared.u64 t, %1; cvt.u32.u64 %0, t; }" : "=r"(a) : "l"(p));
    return a;
}
__device__ __forceinline__ void ldsm4(uint32_t r[4], uint32_t a) {
    asm volatile("ldmatrix.sync.aligned.m8n8.x4.shared.b16 {%0,%1,%2,%3}, [%4];"
                 : "=r"(r[0]), "=r"(r[1]), "=r"(r[2]), "=r"(r[3]) : "r"(a) : "memory");
}
__device__ __forceinline__ void ldsm4t(uint32_t r[4], uint32_t a) {
    asm volatile("ldmatrix.sync.aligned.m8n8.x4.trans.shared.b16 {%0,%1,%2,%3}, [%4];"
                 : "=r"(r[0]), "=r"(r[1]), "=r"(r[2]), "=r"(r[3]) : "r"(a) : "memory");
}
__device__ __forceinline__ void mma16816(float c[4], const uint32_t a[4], uint32_t b0, uint32_t b1) {
    asm volatile(
        "mma.sync.aligned.m16n8k16.row.col.f32.f16.f16.f32 "
        "{%0,%1,%2,%3}, {%4,%5,%6,%7}, {%8,%9}, {%0,%1,%2,%3};"
        : "+f"(c[0]), "+f"(c[1]), "+f"(c[2]), "+f"(c[3])
        : "r"(a[0]), "r"(a[1]), "r"(a[2]), "r"(a[3]), "r"(b0), "r"(b1));
}
__device__ __forceinline__ uint32_t packh2(float x, float y) {
    __half2 h = __floats2half2_rn(x, y);
    return *(uint32_t*)&h;
}
__device__ __forceinline__ float ex2f(float x) {
    float r; asm("ex2.approx.f32 %0, %1;" : "=f"(r) : "f"(x)); return r;
}
__device__ __forceinline__ uint32_t lds_u16(uint32_t a) {
    uint32_t v; asm volatile("ld.shared.u16 %0, [%1];" : "=r"(v) : "r"(a)); return v;
}
#define CPA16(dst, src) asm volatile("cp.async.cg.shared.global [%0], [%1], 16;" :: "r"(dst), "l"(src))
#define CP_COMMIT()     asm volatile("cp.async.commit_group;" ::: "memory")
#define CP_WAIT0()      asm volatile("cp.async.wait_group 0;" ::: "memory")

// ---------------- merged pre-convert kernel ----------------
constexpr int QKV_BLOCKS  = 3 * (BH * Ss * Dd / 4) / 256;       // 12288
constexpr int MASK_BLOCKS = (2 * Ss * Ss / 4) / 256;            // 8192
constexpr float QSCALE = 0.18033688011112042f;                  // log2(e)/8

__global__ void __launch_bounds__(256) cvt_all(const float* __restrict__ Q,
                                               const float* __restrict__ K,
                                               const float* __restrict__ V,
                                               const int* __restrict__ M)
{
    if (blockIdx.x < QKV_BLOCKS) {
        const int n4 = BH * Ss * Dd / 4;
        int id = blockIdx.x * 256 + threadIdx.x;
        const float* src; __half* dst; float s;
        int i = id;
        if (id < n4)          { src = Q; dst = g_qh; s = QSCALE; }
        else if (id < 2 * n4) { src = K; dst = g_kh; s = 1.f; i -= n4; }
        else                  { src = V; dst = g_vh; s = 1.f; i -= 2 * n4; }
        float4 v = ((const float4*)src)[i];
        uint2 u; u.x = packh2(v.x * s, v.y * s); u.y = packh2(v.z * s, v.w * s);
        ((uint2*)dst)[i] = u;
    } else {
        int i = (blockIdx.x - QKV_BLOCKS) * 256 + threadIdx.x;
        int4 m = ((const int4*)M)[i];
        uchar4 o; o.x = (unsigned char)m.x; o.y = (unsigned char)m.y;
        o.z = (unsigned char)m.z; o.w = (unsigned char)m.w;
        ((uchar4*)g_m8)[i] = o;
    }
}

extern __shared__ __align__(16) char sm[];

// ---------------- tile body macros (stage literals A/B) ----------------
#define QK_MMA(KFR)                                                        \
    _Pragma("unroll") for (int kc = 0; kc < 4; kc++)                       \
        _Pragma("unroll") for (int np = 0; np < 4; np++) {                 \
            uint32_t bf[4];                                                \
            ldsm4(bf, (KFR) + np * 2304 + kc * 32);                        \
            mma16816(c[2 * np],     aQ[kc], bf[0], bf[1]);                 \
            mma16816(c[2 * np + 1], aQ[kc], bf[2], bf[3]);                 \
        }

#define P1_BODY(T, CUR, NXT) do {                                          \
    if ((T) + 1 < NT) {                                                    \
        CPA16(kdst##NXT,         kpre);                                    \
        CPA16(kdst##NXT +  4608, kpre + 2048);                             \
        CPA16(kdst##NXT +  9216, kpre + 4096);                             \
        CPA16(kdst##NXT + 13824, kpre + 6144);                             \
        CPA16(mdst##NXT,         mpre);                                    \
        CPA16(mdst##NXT + 4608,  mpre + (size_t)32 * Ss);                  \
        CP_COMMIT();                                                       \
        kpre += (size_t)KT * Dd; mpre += KT;                               \
    }                                                                      \
    float c[8][4];                                                         \
    _Pragma("unroll") for (int nt = 0; nt < 8; nt++) {                     \
        c[nt][0] = 0.f; c[nt][1] = 0.f; c[nt][2] = 0.f; c[nt][3] = 0.f; }  \
    QK_MMA(kfr##CUR)                                                       \
    _Pragma("unroll") for (int nt = 0; nt < 8; nt++) {                     \
        uint32_t m0 = lds_u16(mep##CUR + 8 * nt);                          \
        uint32_t m1 = lds_u16(mep##CUR + 1152 + 8 * nt);                   \
        rs0 += ((m0 & 0xFF) ? ex2f(c[nt][0]) : 0.f)                        \
             + ((m0 >> 8)   ? ex2f(c[nt][1]) : 0.f);                       \
        rs1 += ((m1 & 0xFF) ? ex2f(c[nt][2]) : 0.f)                        \
             + ((m1 >> 8)   ? ex2f(c[nt][3]) : 0.f);                       \
    }                                                                      \
    if ((T) + 1 < NT) { CP_WAIT0(); __syncthreads(); }                     \
} while (0)

#define P2_BODY(T, CUR, NXT) do {                                          \
    if ((T) + 1 < NT) {                                                    \
        CPA16(kdst##NXT,         kpre);                                    \
        CPA16(kdst##NXT +  4608, kpre + 2048);                             \
        CPA16(kdst##NXT +  9216, kpre + 4096);                             \
        CPA16(kdst##NXT + 13824, kpre + 6144);                             \
        CPA16(vdst##NXT,         vpre);                                    \
        CPA16(vdst##NXT +  4608, vpre + 2048);                             \
        CPA16(vdst##NXT +  9216, vpre + 4096);                             \
        CPA16(vdst##NXT + 13824, vpre + 6144);                             \
        CPA16(mdst##NXT,         mpre);                                    \
        CPA16(mdst##NXT + 4608,  mpre + (size_t)32 * Ss);                  \
        CP_COMMIT();                                                       \
        kpre += (size_t)KT * Dd; vpre += (size_t)KT * Dd; mpre += KT;      \
    }                                                                      \
    float c[8][4];                                                         \
    _Pragma("unroll") for (int nt = 0; nt < 8; nt++) {                     \
        c[nt][0] = lr0; c[nt][1] = lr0; c[nt][2] = lr1; c[nt][3] = lr1; }  \
    QK_MMA(kfr##CUR)                                                       \
    _Pragma("unroll") for (int nt = 0; nt < 8; nt++) {                     \
        uint32_t m0 = lds_u16(mep##CUR + 8 * nt);                          \
        uint32_t m1 = lds_u16(mep##CUR + 1152 + 8 * nt);                   \
        float u0 = (m0 & 0xFF) ? ex2f(c[nt][0]) : 0.f;                     \
        float u1 = (m0 >> 8)   ? ex2f(c[nt][1]) : 0.f;                     \
        float u2 = (m1 & 0xFF) ? ex2f(c[nt][2]) : 0.f;                     \
        float u3 = (m1 >> 8)   ? ex2f(c[nt][3]) : 0.f;                     \
        if (ar) {                                                          \
            *(float2*)(ar + 8 * nt)          = make_float2(u0, u1);        \
            *(float2*)(ar + 8 * Ss + 8 * nt) = make_float2(u2, u3);        \
        }                                                                  \
        c[nt][0] = u0; c[nt][1] = u1; c[nt][2] = u2; c[nt][3] = u3;        \
    }                                                                      \
    _Pragma("unroll") for (int kc = 0; kc < 4; kc++) {                     \
        uint32_t a[4];                                                     \
        a[0] = packh2(c[2 * kc][0],     c[2 * kc][1]);                     \
        a[1] = packh2(c[2 * kc][2],     c[2 * kc][3]);                     \
        a[2] = packh2(c[2 * kc + 1][0], c[2 * kc + 1][1]);                 \
        a[3] = packh2(c[2 * kc + 1][2], c[2 * kc + 1][3]);                 \
        _Pragma("unroll") for (int np = 0; np < 4; np++) {                 \
            uint32_t bf[4];                                                \
            ldsm4t(bf, vfr##CUR + kc * 2304 + np * 32);                    \
            mma16816(o[2 * np],     a, bf[0], bf[1]);                      \
            mma16816(o[2 * np + 1], a, bf[2], bf[3]);                      \
        }                                                                  \
    }                                                                      \
    if (ar) ar += KT;                                                      \
    if ((T) + 1 < NT) { CP_WAIT0(); __syncthreads(); }                     \
} while (0)

__global__ void __launch_bounds__(NTH, 2)
attn_kernel(float* __restrict__ out, float* __restrict__ att)
{
    const int tid  = threadIdx.x;
    const int lane = tid & 31;
    const int warp = tid >> 5;
    const int g    = lane >> 2;
    const int tg   = lane & 3;
    const int lm   = lane >> 3;
    const int ll   = lane & 7;
    const int rgrp = warp & 3;         // q-row group (16 rows)
    const int h    = warp >> 2;        // k-col half (64 cols)

    const int q0 = blockIdx.x * QT;
    const int bh = blockIdx.y;
    const int b  = bh >> 4;

    const uint32_t smb = smem_u32(sm);
    float* srows = (float*)(sm + OFF_RED);          // [2][64]
    float* slog  = (float*)(sm + OFF_RED + 512);    // [64]

    const __half* qsrc = g_qh + ((size_t)bh * Ss + q0) * Dd;
    const __half* ksrc = g_kh + (size_t)bh * Ss * Dd;
    const __half* vsrc = g_vh + (size_t)bh * Ss * Dd;
    const unsigned char* msrc = g_m8 + (size_t)b * Ss * Ss + (size_t)q0 * Ss;
    float* attg = att ? (att + (size_t)bh * Ss * (size_t)Ss) : nullptr;

    const int r0 = rgrp * 16 + g;
    const int r1 = r0 + 8;

    // per-thread strength-reduced addresses
    const int lr_ = tid >> 3, lc = tid & 7;
    const uint32_t kdstA = smb + OFF_K + lr_ * 144 + lc * 16;
    const uint32_t kdstB = kdstA + KSTG;
    const uint32_t vdstA = smb + OFF_V + lr_ * 144 + lc * 16;
    const uint32_t vdstB = vdstA + KSTG;
    const uint32_t mdstA = smb + OFF_M + lr_ * 144 + lc * 16;
    const uint32_t mdstB = mdstA + MSTG;
    const __half* ksrcT = ksrc + lr_ * 64 + lc * 8;
    const __half* vsrcT = vsrc + lr_ * 64 + lc * 8;
    const unsigned char* msrcT = msrc + (size_t)lr_ * Ss + lc * 16;

    // fragment bases
    const uint32_t qfr  = smb + OFF_Q + (uint32_t)((rgrp * 16 + (lm & 1) * 8 + ll) * 144 + (lm >> 1) * 16);
    const uint32_t kfrA = smb + OFF_K + (uint32_t)((h * 64 + (lm >> 1) * 8 + ll) * 144 + (lm & 1) * 16);
    const uint32_t kfrB = kfrA + KSTG;
    const uint32_t vfrA = smb + OFF_V + (uint32_t)((h * 64 + (lm & 1) * 8 + ll) * 144 + (lm >> 1) * 16);
    const uint32_t vfrB = vfrA + KSTG;
    const uint32_t mepA = smb + OFF_M + (uint32_t)(r0 * 144 + h * 64 + 2 * tg);
    const uint32_t mepB = mepA + MSTG;

    // ---- pass-1 prologue: Q + K0 + M0 ----
    CPA16(smb + OFF_Q + lr_ * 144 + lc * 16, qsrc + lr_ * 64 + lc * 8);
    CPA16(smb + OFF_Q + (lr_ + 32) * 144 + lc * 16, qsrc + (lr_ + 32) * 64 + lc * 8);
    CPA16(kdstA,         ksrcT);
    CPA16(kdstA +  4608, ksrcT + 2048);
    CPA16(kdstA +  9216, ksrcT + 4096);
    CPA16(kdstA + 13824, ksrcT + 6144);
    CPA16(mdstA,         msrcT);
    CPA16(mdstA + 4608,  msrcT + (size_t)32 * Ss);
    CP_COMMIT(); CP_WAIT0(); __syncthreads();

    uint32_t aQ[4][4];
    #pragma unroll
    for (int kc = 0; kc < 4; kc++) ldsm4(aQ[kc], qfr + kc * 32);

    // ================= PASS 1: row sums =================
    float rs0 = 0.f, rs1 = 0.f;
    {
        const __half* kpre = ksrcT + (size_t)KT * Dd;
        const unsigned char* mpre = msrcT + KT;
        #pragma unroll 1
        for (int t2 = 0; t2 < NT; t2 += 2) {
            P1_BODY(t2,     A, B);
            P1_BODY(t2 + 1, B, A);
        }
    }

    // reduce quad lanes, then the 2 col-halves; logs
    rs0 += __shfl_xor_sync(0xffffffffu, rs0, 1); rs0 += __shfl_xor_sync(0xffffffffu, rs0, 2);
    rs1 += __shfl_xor_sync(0xffffffffu, rs1, 1); rs1 += __shfl_xor_sync(0xffffffffu, rs1, 2);
    if (tg == 0) { srows[h * 64 + r0] = rs0; srows[h * 64 + r1] = rs1; }
    __syncthreads();
    if (tid < 64) {
        float s = srows[tid] + srows[64 + tid];
        slog[tid] = (s > 0.f) ? -__log2f(s) : __int_as_float(0xff800000u);
    }
    __syncthreads();
    const float lr0 = slog[r0];
    const float lr1 = slog[r1];

    // ================= PASS 2: normalized att + O =================
    float o[8][4];
    #pragma unroll
    for (int j = 0; j < 8; j++) { o[j][0] = 0.f; o[j][1] = 0.f; o[j][2] = 0.f; o[j][3] = 0.f; }

    // prologue: K0 + V0 + M0 into stage A
    CPA16(kdstA,         ksrcT);
    CPA16(kdstA +  4608, ksrcT + 2048);
    CPA16(kdstA +  9216, ksrcT + 4096);
    CPA16(kdstA + 13824, ksrcT + 6144);
    CPA16(vdstA,         vsrcT);
    CPA16(vdstA +  4608, vsrcT + 2048);
    CPA16(vdstA +  9216, vsrcT + 4096);
    CPA16(vdstA + 13824, vsrcT + 6144);
    CPA16(mdstA,         msrcT);
    CPA16(mdstA + 4608,  msrcT + (size_t)32 * Ss);
    CP_COMMIT(); CP_WAIT0(); __syncthreads();

    {
        const __half* kpre = ksrcT + (size_t)KT * Dd;
        const __half* vpre = vsrcT + (size_t)KT * Dd;
        const unsigned char* mpre = msrcT + KT;
        float* ar = attg ? (attg + (size_t)(q0 + r0) * Ss + h * 64 + 2 * tg) : nullptr;
        #pragma unroll 1
        for (int t2 = 0; t2 < NT; t2 += 2) {
            P2_BODY(t2,     A, B);
            P2_BODY(t2 + 1, B, A);
        }
    }

    // ---- combine the two k-halves of O via smem (reuse K stage area) ----
    __syncthreads();
    float* ost = (float*)(sm + OFF_K);            // [64][66]
    if (h == 1) {
        #pragma unroll
        for (int j = 0; j < 8; j++) {
            *(float2*)&ost[r0 * 66 + 8 * j + 2 * tg] = make_float2(o[j][0], o[j][1]);
            *(float2*)&ost[r1 * 66 + 8 * j + 2 * tg] = make_float2(o[j][2], o[j][3]);
        }
    }
    __syncthreads();
    if (out && h == 0) {
        float* og0 = out + ((size_t)bh * Ss + q0 + r0) * Dd;
        float* og1 = out + ((size_t)bh * Ss + q0 + r1) * Dd;
        #pragma unroll
        for (int j = 0; j < 8; j++) {
            float2 s0 = *(float2*)&ost[r0 * 66 + 8 * j + 2 * tg];
            float2 s1 = *(float2*)&ost[r1 * 66 + 8 * j + 2 * tg];
            *(float2*)(og0 + 8 * j + 2 * tg) = make_float2(o[j][0] + s0.x, o[j][1] + s0.y);
            *(float2*)(og1 + 8 * j + 2 * tg) = make_float2(o[j][2] + s1.x, o[j][3] + s1.y);
        }
    }
}

extern "C" void kernel_launch(void* const* d_in, const int* in_sizes, int n_in,
                              void* d_out, int out_size)
{
    (void)in_sizes; (void)n_in;
    const float* Q = (const float*)d_in[0];
    const float* K = (const float*)d_in[1];
    const float* V = (const float*)d_in[2];
    const int*   M = (const int*)d_in[3];

    float* outp = nullptr;
    float* attp = nullptr;
    long long os = (long long)out_size;
    if (os >= OUT_ELEMS + ATT_ELEMS) {
        outp = (float*)d_out;
        attp = (float*)d_out + OUT_ELEMS;
    } else if (os >= ATT_ELEMS) {
        attp = (float*)d_out;
    } else {
        outp = (float*)d_out;
    }

    cvt_all<<<QKV_BLOCKS + MASK_BLOCKS, 256>>>(Q, K, V, M);

    cudaFuncSetAttribute(attn_kernel, cudaFuncAttributeMaxDynamicSharedMemorySize, SMEM_BYTES);
    dim3 grid(Ss / QT, BH);
    attn_kernel<<<grid, NTH, SMEM_BYTES>>>(outp, attp);
}